// round 3
// baseline (speedup 1.0000x reference)
#include <cuda_runtime.h>
#include <cuda_bf16.h>

// LightConv1d: out[b,c,t] = sum_{k=0..6} softmax(w[h])[k] * x[b,c,t-6+k] + bias[h]
// h = c % 16. Shapes: x [8,1024,4096] f32, weight [16,1,7] f32, bias [16] f32.
//
// Barrier-free streaming version: no SMEM. Each thread's aligned float4 gives
// win[6..9]; the 6-float causal halo comes from overlapping global loads
// (float2 @ t0-6, float4 @ t0-4) that hit the same 128B lines neighbor lanes
// are already fetching -> L1 miss-merge, no extra DRAM traffic.

#define T_LEN 4096
#define KSZ   7
#define NROWS (8 * 1024)
#define NTHREADS 256
#define NSEG 4   // 256 threads * 4 segments * 4 floats = 4096 = one full row

__global__ __launch_bounds__(NTHREADS)
void lightconv1d_kernel(const float* __restrict__ x,
                        const float* __restrict__ weight,
                        const float* __restrict__ bias,
                        float* __restrict__ out)
{
    const int row = blockIdx.x;          // b*1024 + c
    const int tid = threadIdx.x;

    const float* __restrict__ xr = x + (size_t)row * T_LEN;
    float* __restrict__ orow     = out + (size_t)row * T_LEN;

    // Per-thread softmax of the 7 shared weights for this head (L1-resident).
    const int h = row & 15;              // c % 16
    float wk[KSZ];
    float m = -1e30f;
    #pragma unroll
    for (int k = 0; k < KSZ; ++k) {
        wk[k] = __ldg(&weight[h * KSZ + k]);
        m = fmaxf(m, wk[k]);
    }
    float sum = 0.0f;
    #pragma unroll
    for (int k = 0; k < KSZ; ++k) {
        wk[k] = expf(wk[k] - m);
        sum += wk[k];
    }
    const float inv = 1.0f / sum;
    #pragma unroll
    for (int k = 0; k < KSZ; ++k) wk[k] *= inv;
    const float bv = __ldg(&bias[h]);

    // Front-batch the 4 main loads (MLP_p1 = 4, coalesced 512B per warp-instr).
    float4 v[NSEG];
    #pragma unroll
    for (int seg = 0; seg < NSEG; ++seg)
        v[seg] = reinterpret_cast<const float4*>(xr)[tid + NTHREADS * seg];

    #pragma unroll
    for (int seg = 0; seg < NSEG; ++seg) {
        const int t0 = seg * (NTHREADS * 4) + tid * 4;

        // win[i] = x[t0 - 6 + i], i = 0..9 ; win[6..9] already in v[seg].
        float win[10];
        if (t0 >= 8) {
            // (t0-6)*4 bytes is 8B-aligned, (t0-4)*4 is 16B-aligned.
            const float2 a = *reinterpret_cast<const float2*>(xr + t0 - 6);
            const float4 b = *reinterpret_cast<const float4*>(xr + t0 - 4);
            win[0] = a.x; win[1] = a.y;
            win[2] = b.x; win[3] = b.y; win[4] = b.z; win[5] = b.w;
        } else {
            // Only seg==0, tid<2: causal zero padding at the row start.
            #pragma unroll
            for (int i = 0; i < 6; ++i) {
                const int idx = t0 - 6 + i;
                win[i] = (idx >= 0) ? xr[idx] : 0.0f;
            }
        }
        win[6] = v[seg].x; win[7] = v[seg].y; win[8] = v[seg].z; win[9] = v[seg].w;

        float acc0 = bv, acc1 = bv, acc2 = bv, acc3 = bv;
        #pragma unroll
        for (int k = 0; k < KSZ; ++k) {
            acc0 = fmaf(wk[k], win[k + 0], acc0);
            acc1 = fmaf(wk[k], win[k + 1], acc1);
            acc2 = fmaf(wk[k], win[k + 2], acc2);
            acc3 = fmaf(wk[k], win[k + 3], acc3);
        }
        float4 r;
        r.x = acc0; r.y = acc1; r.z = acc2; r.w = acc3;
        reinterpret_cast<float4*>(orow)[tid + NTHREADS * seg] = r;
    }
}

extern "C" void kernel_launch(void* const* d_in, const int* in_sizes, int n_in,
                              void* d_out, int out_size)
{
    const float* x      = (const float*)d_in[0];
    const float* weight = (const float*)d_in[1];
    const float* bias   = (const float*)d_in[2];
    float* out          = (float*)d_out;

    lightconv1d_kernel<<<NROWS, NTHREADS>>>(x, weight, bias, out);
}